// round 12
// baseline (speedup 1.0000x reference)
#include <cuda_runtime.h>
#include <float.h>
#include <math.h>

#define MAXROWS 8192
#define D32     32000
#define NT1     512
#define NW1     (NT1 / 32)
#define KFULL   15             // 8000 f4 = 15*512 + 320
#define REM     320
#define NT2     256            // 8 row-warps per block
#define WPB     8
#define WCAP    24             // per-lane candidate floats

__device__ float    g_rowmax[MAXROWS];
__device__ unsigned g_mask[MAXROWS * NT1];
__device__ float    g_rowloss[MAXROWS];

#define M4(v) fmaxf(fmaxf((v).x, (v).y), fmaxf((v).z, (v).w))

__device__ __forceinline__ float warpMax(float v) {
#pragma unroll
    for (int o = 16; o; o >>= 1) v = fmaxf(v, __shfl_xor_sync(0xffffffffu, v, o));
    return v;
}
__device__ __forceinline__ float warpSumB(float v) {   // uniform, deterministic
#pragma unroll
    for (int o = 16; o; o >>= 1) v += __shfl_xor_sync(0xffffffffu, v, o);
    return v;
}

// ============ K1 (d==32000): pure rowmax stream + exact-threshold bits ============
// Measured 79.5 us @ 85% DRAM. Threshold rowmax-2.0 => kept = exactly {X > maxX-1},
// sufficient for EVERY bisection probe (tau_m > tau_lo0 = maxX-1 always).
__global__ __launch_bounds__(NT1, 2) void filter32k(const float* __restrict__ in) {
    int row = blockIdx.x, tid = threadIdx.x;
    int lane = tid & 31, warp = tid >> 5;
    const float4* p4 = (const float4*)(in + (size_t)row * D32);
    __shared__ float swm[NW1];

    float m4[KFULL + 1];
#pragma unroll
    for (int k = 0; k < KFULL; k++) {
        float4 v = p4[k * NT1 + tid];
        m4[k] = M4(v);
    }
    if (tid < REM) {
        float4 v = p4[KFULL * NT1 + tid];
        m4[KFULL] = M4(v);
    } else m4[KFULL] = -FLT_MAX;

    float rm = m4[0];
#pragma unroll
    for (int k = 1; k <= KFULL; k++) rm = fmaxf(rm, m4[k]);

    float wv = warpMax(rm);
    if (lane == 0) swm[warp] = wv;
    __syncthreads();
    float bmax = swm[0];
#pragma unroll
    for (int w = 1; w < NW1; w++) bmax = fmaxf(bmax, swm[w]);

    float th = bmax - 2.0f;
    unsigned hit = 0;
#pragma unroll
    for (int k = 0; k <= KFULL; k++)
        if (m4[k] > th) hit |= (1u << k);

    g_mask[row * NT1 + tid] = hit;
    if (tid == 0) g_rowmax[row] = bmax;
}

// ============ K2 (d==32000): WARP-per-row tail, zero barriers ============
__global__ __launch_bounds__(NT2) void bisect32k(const float* __restrict__ in,
                                                 const void* __restrict__ tgt, int n) {
    int lane = threadIdx.x & 31;
    int w    = threadIdx.x >> 5;
    int row  = blockIdx.x * WPB + w;
    __shared__ float cand[WPB][WCAP][32];     // 24 KB
    if (row >= n) return;                     // no barriers anywhere below

    const float* xr = in + (size_t)row * D32;
    const float4* p4 = (const float4*)xr;

    float bmax    = g_rowmax[row];
    float maxX    = 0.5f * bmax;
    float thr     = bmax - 2.0f;              // raw; exact support of tau_lo0
    float tau_lo0 = maxX - 1.0f;
    float tau_hi0 = maxX - 0.00559017f;       // maxX - (1/32000)^0.5

    // ---- gather: 16 coalesced mask words per lane -> private smem column ----
    int cnt = 0;
#pragma unroll 1
    for (int j = 0; j < 16; j++) {
        int c = lane + 32 * j;                // K1 column 0..511
        unsigned hm = g_mask[row * NT1 + c];
        while (hm) {
            int b = __ffs(hm) - 1;
            hm &= hm - 1;
            float4 v = p4[b * NT1 + c];
            if (v.x > thr) { if (cnt < WCAP) cand[w][cnt][lane] = 0.5f * v.x; cnt++; }
            if (v.y > thr) { if (cnt < WCAP) cand[w][cnt][lane] = 0.5f * v.y; cnt++; }
            if (v.z > thr) { if (cnt < WCAP) cand[w][cnt][lane] = 0.5f * v.z; cnt++; }
            if (v.w > thr) { if (cnt < WCAP) cand[w][cnt][lane] = 0.5f * v.w; cnt++; }
        }
    }
    bool slow = __any_sync(0xffffffffu, cnt > WCAP);
    int  myc  = slow ? 0 : cnt;

    float S3, PX, tau_m;
    if (!slow) {
        // ---- f_lo over cand (== exact f_lo; order deterministic) ----
        float fl = 0.f;
        for (int j = 0; j < myc; j++) {
            float t = cand[w][j][lane] - tau_lo0;
            if (t > 0.f) fl = fmaf(t, t, fl);
        }
        float f_lo = warpSumB(fl) - 1.0f;

        // ---- 15 bisection iterations, warp-local ----
        float tau_lo = tau_lo0;
        float dm     = tau_hi0 - tau_lo0;
        tau_m = tau_lo0;
#pragma unroll 1
        for (int it = 0; it < 15; it++) {
            dm *= 0.5f;
            tau_m = tau_lo + dm;
            float s = 0.f;
            for (int j = 0; j < myc; j++) {
                float t = fmaxf(cand[w][j][lane] - tau_m, 0.f);
                s = fmaf(t, t, s);
            }
            float fm = warpSumB(s) - 1.0f;
            tau_lo = (fm * f_lo >= 0.f) ? tau_m : tau_lo;   // uniform
        }

        // ---- finals ----
        float s3 = 0.f, px = 0.f;
        for (int j = 0; j < myc; j++) {
            float X = cand[w][j][lane];
            float t = fmaxf(X - tau_m, 0.f);
            float p = t * t;
            s3 = fmaf(p, t, s3);
            px = fmaf(p, X, px);
        }
        S3 = warpSumB(s3);
        PX = warpSumB(px);
    } else {
        // ---- warp-local full-reference slow path (overflow only, ~never) ----
        float tl = tau_lo0;
        float s0 = 0.f;
        for (int i = lane; i < D32; i += 32) {
            float q = fmaxf(fmaf(0.5f, __ldg(xr + i), -tl), 0.f);
            s0 = fmaf(q, q, s0);
        }
        float f_lo = warpSumB(s0) - 1.0f;
        float dm = tau_hi0 - tl, tm = tl;
#pragma unroll 1
        for (int it = 0; it < 15; it++) {
            dm *= 0.5f;
            tm = tl + dm;
            float q2 = 0.f;
            for (int i = lane; i < D32; i += 32) {
                float q = fmaxf(fmaf(0.5f, __ldg(xr + i), -tm), 0.f);
                q2 = fmaf(q, q, q2);
            }
            float fm = warpSumB(q2) - 1.0f;
            tl = (fm * f_lo >= 0.f) ? tm : tl;
        }
        tau_m = tm;
        float s3 = 0.f, px = 0.f;
        for (int i = lane; i < D32; i += 32) {
            float X = 0.5f * __ldg(xr + i);
            float t = fmaxf(X - tau_m, 0.f);
            float p = t * t;
            s3 = fmaf(p, t, s3);
            px = fmaf(p, X, px);
        }
        S3 = warpSumB(s3);
        PX = warpSumB(px);
    }

    // ---- target (lane-parallel dtype sniff) + loss ----
    {
        const int* t32 = (const int*)tgt;
        int lim = (n < 32) ? n : 32;
        int z = 1;
        if (lane < lim) z = (t32[2 * lane + 1] == 0);
        bool is64 = __all_sync(0xffffffffu, z != 0);
        if (lane == 0) {
            long long v = is64 ? ((const long long*)tgt)[row] : (long long)t32[row];
            int t = (int)v;
            if (t < 0 || t >= D32) t = 0;
            float xt = __ldg(xr + t);
            // loss = (1-S3)/(alpha*(alpha-1)) + sum(p*input) - input[target]
            //      = (1-S3)/0.75 + 2*PX - xt          (input = 2*X)
            g_rowloss[row] = (1.0f - S3) / 0.75f + 2.0f * PX - xt;
        }
    }
}

// ============ generic fallback (any d) ============
__device__ __forceinline__ float blockSumAllG(float v, float* sbuf) {
    int lane = threadIdx.x & 31, warp = threadIdx.x >> 5;
#pragma unroll
    for (int o = 16; o; o >>= 1) v += __shfl_xor_sync(0xffffffffu, v, o);
    __syncthreads();
    if (lane == 0) sbuf[warp] = v;
    __syncthreads();
    float s = 0.f;
#pragma unroll
    for (int w = 0; w < 8; w++) s += sbuf[w];
    return s;
}
__global__ __launch_bounds__(256) void tsallis_gen(const float* __restrict__ in,
                                                   const void* __restrict__ tgt,
                                                   int d, int n) {
    int row = blockIdx.x;
    const float* xr = in + (size_t)row * d;
    __shared__ float sred[8];
    float m = -FLT_MAX;
    for (int i = threadIdx.x; i < d; i += 256) m = fmaxf(m, xr[i]);
    m = warpMax(m);
    __syncthreads();
    if ((threadIdx.x & 31) == 0) sred[threadIdx.x >> 5] = m;
    __syncthreads();
    float bmax = sred[0];
#pragma unroll
    for (int w = 1; w < 8; w++) bmax = fmaxf(bmax, sred[w]);
    float maxX = 0.5f * bmax;
    float tl = maxX - 1.0f;
    float th0 = maxX - (float)(1.0 / sqrt((double)d));
    float s = 0.f;
    for (int i = threadIdx.x; i < d; i += 256) {
        float q = fmaxf(fmaf(0.5f, __ldg(xr + i), -tl), 0.f);
        s = fmaf(q, q, s);
    }
    float f_lo = blockSumAllG(s, sred) - 1.0f;
    float dm = th0 - tl, tm = tl;
#pragma unroll 1
    for (int it = 0; it < 15; it++) {
        dm *= 0.5f;
        tm = tl + dm;
        float q2 = 0.f;
        for (int i = threadIdx.x; i < d; i += 256) {
            float q = fmaxf(fmaf(0.5f, __ldg(xr + i), -tm), 0.f);
            q2 = fmaf(q, q, q2);
        }
        float fm = blockSumAllG(q2, sred) - 1.0f;
        tl = (fm * f_lo >= 0.f) ? tm : tl;
    }
    float s3 = 0.f, px = 0.f;
    for (int i = threadIdx.x; i < d; i += 256) {
        float X = 0.5f * __ldg(xr + i);
        float q = fmaxf(X - tm, 0.f);
        float p = q * q;
        s3 = fmaf(p, q, s3);
        px = fmaf(p, X, px);
    }
    float S3 = blockSumAllG(s3, sred);
    float PX = blockSumAllG(px, sred);
    if (threadIdx.x == 0) {
        const int* t32 = (const int*)tgt;
        int lim = (n < 32) ? n : 32;
        bool is64 = true;
        for (int i = 0; i < lim; i++) is64 = is64 && (t32[2 * i + 1] == 0);
        long long v = is64 ? ((const long long*)tgt)[row] : (long long)t32[row];
        int t = (int)v;
        if (t < 0 || t >= d) t = 0;
        g_rowloss[row] = (1.0f - S3) / 0.75f + 2.0f * PX - __ldg(xr + t);
    }
}

// ============ mean over rows ============
__global__ __launch_bounds__(1024) void reduce_kernel(float* __restrict__ out, int n) {
    __shared__ float sbuf[32];
    float s = 0.f;
    for (int i = threadIdx.x; i < n; i += 1024) s += g_rowloss[i];
#pragma unroll
    for (int o = 16; o; o >>= 1) s += __shfl_down_sync(0xffffffffu, s, o);
    if ((threadIdx.x & 31) == 0) sbuf[threadIdx.x >> 5] = s;
    __syncthreads();
    if (threadIdx.x < 32) {
        float x = sbuf[threadIdx.x];
#pragma unroll
        for (int o = 16; o; o >>= 1) x += __shfl_down_sync(0xffffffffu, x, o);
        if (threadIdx.x == 0) out[0] = x / (float)n;
    }
}

extern "C" void kernel_launch(void* const* d_in, const int* in_sizes, int n_in,
                              void* d_out, int out_size) {
    int idx_in = 0, idx_tg = 1;
    if (n_in >= 2 && in_sizes[1] > in_sizes[0]) { idx_in = 1; idx_tg = 0; }
    const float* in  = (const float*)d_in[idx_in];
    const void*  tgt = d_in[idx_tg];

    int n = in_sizes[idx_tg];
    if (n <= 0) n = 1;
    int d = in_sizes[idx_in] / n;
    if (n > MAXROWS) n = MAXROWS;

    if (d == D32) {
        filter32k<<<n, NT1>>>(in);
        bisect32k<<<(n + WPB - 1) / WPB, NT2>>>(in, tgt, n);
    } else {
        tsallis_gen<<<n, 256>>>(in, tgt, d, n);
    }
    reduce_kernel<<<1, 1024>>>((float*)d_out, n);
}

// round 13
// speedup vs baseline: 8.7337x; 8.7337x over previous
#include <cuda_runtime.h>
#include <float.h>
#include <math.h>

#define MAXROWS 8192
#define D32     32000
#define NT1     512
#define NW1     (NT1 / 32)
#define KFULL   15             // 8000 f4 = 15*512 + 320
#define REM     320
#define NT2     256
#define WPB     8              // row-warps per K2 block
#define SCAP    2048           // pooled f4 slots per row (global scratch)

__device__ float    g_rowmax[MAXROWS];
__device__ unsigned g_mask[MAXROWS * NT1];
__device__ int      g_flag[MAXROWS];
__device__ float4   g_pool[MAXROWS * SCAP];    // 268 MB scratch
__device__ float    g_rowloss[MAXROWS];

#define M4(v) fmaxf(fmaxf((v).x, (v).y), fmaxf((v).z, (v).w))

__device__ __forceinline__ float warpMax(float v) {
#pragma unroll
    for (int o = 16; o; o >>= 1) v = fmaxf(v, __shfl_xor_sync(0xffffffffu, v, o));
    return v;
}
__device__ __forceinline__ float warpSumB(float v) {   // uniform, deterministic
#pragma unroll
    for (int o = 16; o; o >>= 1) v += __shfl_xor_sync(0xffffffffu, v, o);
    return v;
}

// ============ K1 (d==32000): pure rowmax stream + exact-threshold bits ============
// Measured 79.5 us @ 85% DRAM. Bit set iff f4max > rowmax-2 <=> f4 contains an
// element with X > maxX-1 = tau_lo0, a superset of every bisection probe's support.
__global__ __launch_bounds__(NT1, 2) void filter32k(const float* __restrict__ in) {
    int row = blockIdx.x, tid = threadIdx.x;
    int lane = tid & 31, warp = tid >> 5;
    const float4* p4 = (const float4*)(in + (size_t)row * D32);
    __shared__ float swm[NW1];

    float m4[KFULL + 1];
#pragma unroll
    for (int k = 0; k < KFULL; k++) {
        float4 v = p4[k * NT1 + tid];
        m4[k] = M4(v);
    }
    if (tid < REM) {
        float4 v = p4[KFULL * NT1 + tid];
        m4[KFULL] = M4(v);
    } else m4[KFULL] = -FLT_MAX;

    float rm = m4[0];
#pragma unroll
    for (int k = 1; k <= KFULL; k++) rm = fmaxf(rm, m4[k]);

    float wv = warpMax(rm);
    if (lane == 0) swm[warp] = wv;
    __syncthreads();
    float bmax = swm[0];
#pragma unroll
    for (int w = 1; w < NW1; w++) bmax = fmaxf(bmax, swm[w]);

    float th = bmax - 2.0f;
    unsigned hit = 0;
#pragma unroll
    for (int k = 0; k <= KFULL; k++)
        if (m4[k] > th) hit |= (1u << k);

    g_mask[row * NT1 + tid] = hit;
    if (tid == 0) g_rowmax[row] = bmax;
}

// ============ K2 (d==32000): warp-per-row pooled gather + bisection ============
__global__ __launch_bounds__(NT2) void bisect32k(const float* __restrict__ in,
                                                 const void* __restrict__ tgt, int n) {
    int lane = threadIdx.x & 31;
    int w    = threadIdx.x >> 5;
    int row  = blockIdx.x * WPB + w;
    if (row >= n) return;                       // warp-autonomous

    const float* xr = in + (size_t)row * D32;
    const float4* p4 = (const float4*)xr;

    // ---- read masks (coalesced, independent) + popcount ----
    unsigned hm[16];
    int tl = 0;
#pragma unroll
    for (int j = 0; j < 16; j++) {
        hm[j] = g_mask[row * NT1 + lane + 32 * j];
        tl += __popc(hm[j]);
    }
    // warp exclusive scan of per-lane counts (deterministic positions)
    int incl = tl;
#pragma unroll
    for (int o = 1; o < 32; o <<= 1) {
        int t = __shfl_up_sync(0xffffffffu, incl, o);
        if (lane >= o) incl += t;
    }
    int total = __shfl_sync(0xffffffffu, incl, 31);
    int base  = incl - tl;

    bool ovf = (total > SCAP);
    if (lane == 0) g_flag[row] = ovf ? 1 : 0;
    if (ovf) return;                            // K3 handles this row

    // ---- gather: independent scattered loads -> pooled global scratch ----
    float4* pool = g_pool + (size_t)row * SCAP;
    {
        int pos = base;
#pragma unroll
        for (int j = 0; j < 16; j++) {
            unsigned m = hm[j];
            int c = lane + 32 * j;
            while (m) {
                int b = __ffs(m) - 1;
                m &= m - 1;
                pool[pos++] = p4[b * NT1 + c];  // positions mask-derived: full MLP
            }
        }
    }
    __threadfence_block();
    __syncwarp();

    float bmax    = g_rowmax[row];
    float maxX    = 0.5f * bmax;
    float tau_lo0 = maxX - 1.0f;
    float tau_hi0 = maxX - 0.00559017f;         // maxX - (1/32000)^0.5

    // ---- f_lo over pool (exact: excluded elements contribute 0) ----
    float fl = 0.f;
    for (int i = lane; i < total; i += 32) {
        float4 v = pool[i];
        float q;
        q = fmaxf(fmaf(0.5f, v.x, -tau_lo0), 0.f); fl = fmaf(q, q, fl);
        q = fmaxf(fmaf(0.5f, v.y, -tau_lo0), 0.f); fl = fmaf(q, q, fl);
        q = fmaxf(fmaf(0.5f, v.z, -tau_lo0), 0.f); fl = fmaf(q, q, fl);
        q = fmaxf(fmaf(0.5f, v.w, -tau_lo0), 0.f); fl = fmaf(q, q, fl);
    }
    float f_lo = warpSumB(fl) - 1.0f;

    // ---- 15 bisection iterations (pool is L1-resident after iter 1) ----
    float tau_lo = tau_lo0;
    float dm     = tau_hi0 - tau_lo0;
    float tau_m  = tau_lo0;
#pragma unroll 1
    for (int it = 0; it < 15; it++) {
        dm *= 0.5f;
        tau_m = tau_lo + dm;
        float s = 0.f;
        for (int i = lane; i < total; i += 32) {
            float4 v = pool[i];
            float q;
            q = fmaxf(fmaf(0.5f, v.x, -tau_m), 0.f); s = fmaf(q, q, s);
            q = fmaxf(fmaf(0.5f, v.y, -tau_m), 0.f); s = fmaf(q, q, s);
            q = fmaxf(fmaf(0.5f, v.z, -tau_m), 0.f); s = fmaf(q, q, s);
            q = fmaxf(fmaf(0.5f, v.w, -tau_m), 0.f); s = fmaf(q, q, s);
        }
        float fm = warpSumB(s) - 1.0f;
        tau_lo = (fm * f_lo >= 0.f) ? tau_m : tau_lo;   // uniform across warp
    }

    // ---- finals at last tau_m ----
    float s3 = 0.f, px = 0.f;
    for (int i = lane; i < total; i += 32) {
        float4 v = pool[i];
        float X, q, p;
        X = 0.5f * v.x; q = fmaxf(X - tau_m, 0.f); p = q * q; s3 = fmaf(p, q, s3); px = fmaf(p, X, px);
        X = 0.5f * v.y; q = fmaxf(X - tau_m, 0.f); p = q * q; s3 = fmaf(p, q, s3); px = fmaf(p, X, px);
        X = 0.5f * v.z; q = fmaxf(X - tau_m, 0.f); p = q * q; s3 = fmaf(p, q, s3); px = fmaf(p, X, px);
        X = 0.5f * v.w; q = fmaxf(X - tau_m, 0.f); p = q * q; s3 = fmaf(p, q, s3); px = fmaf(p, X, px);
    }
    float S3 = warpSumB(s3);
    float PX = warpSumB(px);

    // ---- target (lane-parallel dtype sniff) + loss ----
    {
        const int* t32 = (const int*)tgt;
        int lim = (n < 32) ? n : 32;
        int z = 1;
        if (lane < lim) z = (t32[2 * lane + 1] == 0);
        bool is64 = __all_sync(0xffffffffu, z != 0);
        if (lane == 0) {
            long long v = is64 ? ((const long long*)tgt)[row] : (long long)t32[row];
            int t = (int)v;
            if (t < 0 || t >= D32) t = 0;
            float xt = __ldg(xr + t);
            // loss = (1-S3)/(alpha*(alpha-1)) + sum(p*input) - input[target]
            //      = (1-S3)/0.75 + 2*PX - xt          (input = 2*X)
            g_rowloss[row] = (1.0f - S3) / 0.75f + 2.0f * PX - xt;
        }
    }
}

// ============ shared block-parallel reference core ============
__device__ __forceinline__ float blockSumAllG(float v, float* sbuf) {
    int lane = threadIdx.x & 31, warp = threadIdx.x >> 5;
#pragma unroll
    for (int o = 16; o; o >>= 1) v += __shfl_xor_sync(0xffffffffu, v, o);
    __syncthreads();
    if (lane == 0) sbuf[warp] = v;
    __syncthreads();
    float s = 0.f;
#pragma unroll
    for (int w = 0; w < 8; w++) s += sbuf[w];
    return s;
}

__device__ void ref_row(const float* xr, const void* tgt, int d, int n, int row,
                        float* sred) {
    float m = -FLT_MAX;
    for (int i = threadIdx.x; i < d; i += 256) m = fmaxf(m, xr[i]);
    m = warpMax(m);
    __syncthreads();
    if ((threadIdx.x & 31) == 0) sred[threadIdx.x >> 5] = m;
    __syncthreads();
    float bmax = sred[0];
#pragma unroll
    for (int w = 1; w < 8; w++) bmax = fmaxf(bmax, sred[w]);
    float maxX = 0.5f * bmax;
    float tl = maxX - 1.0f;
    float th0 = maxX - (float)(1.0 / sqrt((double)d));
    float s = 0.f;
    for (int i = threadIdx.x; i < d; i += 256) {
        float q = fmaxf(fmaf(0.5f, __ldg(xr + i), -tl), 0.f);
        s = fmaf(q, q, s);
    }
    float f_lo = blockSumAllG(s, sred) - 1.0f;
    float dm = th0 - tl, tm = tl;
#pragma unroll 1
    for (int it = 0; it < 15; it++) {
        dm *= 0.5f;
        tm = tl + dm;
        float q2 = 0.f;
        for (int i = threadIdx.x; i < d; i += 256) {
            float q = fmaxf(fmaf(0.5f, __ldg(xr + i), -tm), 0.f);
            q2 = fmaf(q, q, q2);
        }
        float fm = blockSumAllG(q2, sred) - 1.0f;
        tl = (fm * f_lo >= 0.f) ? tm : tl;
    }
    float s3 = 0.f, px = 0.f;
    for (int i = threadIdx.x; i < d; i += 256) {
        float X = 0.5f * __ldg(xr + i);
        float q = fmaxf(X - tm, 0.f);
        float p = q * q;
        s3 = fmaf(p, q, s3);
        px = fmaf(p, X, px);
    }
    float S3 = blockSumAllG(s3, sred);
    float PX = blockSumAllG(px, sred);
    if (threadIdx.x == 0) {
        const int* t32 = (const int*)tgt;
        int lim = (n < 32) ? n : 32;
        bool is64 = true;
        for (int i = 0; i < lim; i++) is64 = is64 && (t32[2 * i + 1] == 0);
        long long v = is64 ? ((const long long*)tgt)[row] : (long long)t32[row];
        int t = (int)v;
        if (t < 0 || t >= d) t = 0;
        g_rowloss[row] = (1.0f - S3) / 0.75f + 2.0f * PX - __ldg(xr + t);
    }
}

// K3: flagged (overflow) rows only; everyone else exits immediately.
__global__ __launch_bounds__(256) void flagged32k(const float* __restrict__ in,
                                                  const void* __restrict__ tgt, int n) {
    int row = blockIdx.x;
    if (!g_flag[row]) return;
    __shared__ float sred[8];
    ref_row(in + (size_t)row * D32, tgt, D32, n, row, sred);
}

// generic fallback (any d)
__global__ __launch_bounds__(256) void tsallis_gen(const float* __restrict__ in,
                                                   const void* __restrict__ tgt,
                                                   int d, int n) {
    int row = blockIdx.x;
    __shared__ float sred[8];
    ref_row(in + (size_t)row * d, tgt, d, n, row, sred);
}

// mean over rows
__global__ __launch_bounds__(1024) void reduce_kernel(float* __restrict__ out, int n) {
    __shared__ float sbuf[32];
    float s = 0.f;
    for (int i = threadIdx.x; i < n; i += 1024) s += g_rowloss[i];
#pragma unroll
    for (int o = 16; o; o >>= 1) s += __shfl_down_sync(0xffffffffu, s, o);
    if ((threadIdx.x & 31) == 0) sbuf[threadIdx.x >> 5] = s;
    __syncthreads();
    if (threadIdx.x < 32) {
        float x = sbuf[threadIdx.x];
#pragma unroll
        for (int o = 16; o; o >>= 1) x += __shfl_down_sync(0xffffffffu, x, o);
        if (threadIdx.x == 0) out[0] = x / (float)n;
    }
}

extern "C" void kernel_launch(void* const* d_in, const int* in_sizes, int n_in,
                              void* d_out, int out_size) {
    int idx_in = 0, idx_tg = 1;
    if (n_in >= 2 && in_sizes[1] > in_sizes[0]) { idx_in = 1; idx_tg = 0; }
    const float* in  = (const float*)d_in[idx_in];
    const void*  tgt = d_in[idx_tg];

    int n = in_sizes[idx_tg];
    if (n <= 0) n = 1;
    int d = in_sizes[idx_in] / n;
    if (n > MAXROWS) n = MAXROWS;

    if (d == D32) {
        filter32k<<<n, NT1>>>(in);
        bisect32k<<<(n + WPB - 1) / WPB, NT2>>>(in, tgt, n);
        flagged32k<<<n, 256>>>(in, tgt, n);
    } else {
        tsallis_gen<<<n, 256>>>(in, tgt, d, n);
    }
    reduce_kernel<<<1, 1024>>>((float*)d_out, n);
}